// round 4
// baseline (speedup 1.0000x reference)
#include <cuda_runtime.h>
#include <cstdint>

// Attention with exact JAX threefry dropout (partitionable path: bits1 ^ bits2).
// B=1, S=N=4096, H=16, D=64. out[s,h',d] scatter per reference reshape chain.

#define NSEQ 4096
#define NHEAD 16
#define HDIM 64
#define BM 64
#define BN 64

// ---------------- threefry2x32 with key (0, 42) ----------------
// ks = [0, 42, 0 ^ 42 ^ 0x1BD11BDA = 0x1BD11BF0]
__device__ __forceinline__ void tf_g0(uint32_t& a, uint32_t& b) { // rots 13,15,26,6
    a += b; b = __funnelshift_l(b, b, 13); b ^= a;
    a += b; b = __funnelshift_l(b, b, 15); b ^= a;
    a += b; b = __funnelshift_l(b, b, 26); b ^= a;
    a += b; b = __funnelshift_l(b, b, 6);  b ^= a;
}
__device__ __forceinline__ void tf_g1(uint32_t& a, uint32_t& b) { // rots 17,29,16,24
    a += b; b = __funnelshift_l(b, b, 17); b ^= a;
    a += b; b = __funnelshift_l(b, b, 29); b ^= a;
    a += b; b = __funnelshift_l(b, b, 16); b ^= a;
    a += b; b = __funnelshift_l(b, b, 24); b ^= a;
}

// Partitionable threefry bits for element index e < 2^28:
// counters (x0, x1) = (hi32(e), lo32(e)) = (0, e);
// 32-bit draw = bits1 ^ bits2 (XOR of the two output lanes).
// keep  <=>  bitcast((bits>>9)|0x3f800000) - 1 < 0.9f  <=>  (bits>>9) < 7549747
__device__ __forceinline__ bool keep_mask(uint32_t e) {
    uint32_t a = 0u;        // x0 + ks0
    uint32_t b = e + 42u;   // x1 + ks1
    tf_g0(a, b); a += 42u;          b += 0x1BD11BF1u;  // ks1 | ks2+1
    tf_g1(a, b); a += 0x1BD11BF0u;  b += 2u;           // ks2 | ks0+2
    tf_g0(a, b); /* a += ks0 */     b += 45u;          // ks0 | ks1+3
    tf_g1(a, b); a += 42u;          b += 0x1BD11BF4u;  // ks1 | ks2+4
    tf_g0(a, b); a += 0x1BD11BF0u;  b += 5u;           // ks2 | ks0+5
    return ((a ^ b) >> 9) < 7549747u;   // bits1 ^ bits2
}

// ---------------- swizzled transposed smem tile ----------------
// Tile stored as [row][64 floats]; float4 chunk c of row d lives at chunk (c ^ (d&15)).
__device__ __forceinline__ void store_T(float* T, int d, int i, float val) {
    T[(d << 6) + ((((i >> 2)) ^ (d & 15)) << 2) + (i & 3)] = val;
}

__global__ __launch_bounds__(256, 2)
void attn_kernel(const float* __restrict__ q, const float* __restrict__ k,
                 const float* __restrict__ v, float* __restrict__ out)
{
    __shared__ float Qt[64 * 64];   // Q transposed [d][i], swizzled
    __shared__ float KPt[64 * 64];  // K transposed [d][j] then P transposed [j][i], swizzled
    __shared__ float Vs[64 * 64];   // V row-major [j][dv]

    const int tid = threadIdx.x;
    const int tx = tid & 15;
    const int ty = tid >> 4;
    const int h = blockIdx.y;
    const int iBase = blockIdx.x * BM;
    const uint32_t hbase = ((uint32_t)h) << 24;

    const float* qbase = q + h * HDIM + iBase * (NHEAD * HDIM);
    const float* kbase = k + h * HDIM;
    const float* vbase = v + h * HDIM;

    // Load Q tile, transposed+swizzled (one time)
#pragma unroll
    for (int it = 0; it < 4; it++) {
        int pos = tid + it * 256;     // 0..1023
        int row = pos >> 4;           // i in [0,64)
        int c4 = pos & 15;            // float4 index along d
        float4 g = *reinterpret_cast<const float4*>(qbase + row * 1024 + c4 * 4);
        int d0 = c4 << 2;
        store_T(Qt, d0 + 0, row, g.x);
        store_T(Qt, d0 + 1, row, g.y);
        store_T(Qt, d0 + 2, row, g.z);
        store_T(Qt, d0 + 3, row, g.w);
    }

    float m_r[4], l_r[4], acc[4][4];
#pragma unroll
    for (int r = 0; r < 4; r++) {
        m_r[r] = -1e30f;
        l_r[r] = 0.0f;
#pragma unroll
        for (int c = 0; c < 4; c++) acc[r][c] = 0.0f;
    }

    for (int jt = 0; jt < NSEQ / BN; jt++) {
        const int j0 = jt * BN;
        __syncthreads();  // previous PV reads of KPt/Vs done

        // Load K (transposed+swizzled) and V (row-major) tiles
#pragma unroll
        for (int it = 0; it < 4; it++) {
            int pos = tid + it * 256;
            int row = pos >> 4;
            int c4 = pos & 15;
            const float* kp = kbase + (j0 + row) * 1024 + c4 * 4;
            float4 gk = *reinterpret_cast<const float4*>(kp);
            int d0 = c4 << 2;
            store_T(KPt, d0 + 0, row, gk.x);
            store_T(KPt, d0 + 1, row, gk.y);
            store_T(KPt, d0 + 2, row, gk.z);
            store_T(KPt, d0 + 3, row, gk.w);
            const float* vp = vbase + (j0 + row) * 1024 + c4 * 4;
            float4 gv = *reinterpret_cast<const float4*>(vp);
            *reinterpret_cast<float4*>(&Vs[(row << 6) + (c4 << 2)]) = gv;
        }
        __syncthreads();

        // S = (Q K^T) / 8
        float s[4][4];
#pragma unroll
        for (int r = 0; r < 4; r++)
#pragma unroll
            for (int c = 0; c < 4; c++) s[r][c] = 0.0f;

#pragma unroll 16
        for (int d = 0; d < 64; d++) {
            float4 av4 = *reinterpret_cast<const float4*>(&Qt[(d << 6) + ((ty ^ (d & 15)) << 2)]);
            float4 bv4 = *reinterpret_cast<const float4*>(&KPt[(d << 6) + ((tx ^ (d & 15)) << 2)]);
            float av[4] = {av4.x, av4.y, av4.z, av4.w};
            float bv[4] = {bv4.x, bv4.y, bv4.z, bv4.w};
#pragma unroll
            for (int r = 0; r < 4; r++)
#pragma unroll
                for (int c = 0; c < 4; c++) s[r][c] = fmaf(av[r], bv[c], s[r][c]);
        }
#pragma unroll
        for (int r = 0; r < 4; r++)
#pragma unroll
            for (int c = 0; c < 4; c++) s[r][c] *= 0.125f;

        // Online softmax (unmasked denominator!)
#pragma unroll
        for (int r = 0; r < 4; r++) {
            float mx = fmaxf(fmaxf(s[r][0], s[r][1]), fmaxf(s[r][2], s[r][3]));
            mx = fmaxf(mx, __shfl_xor_sync(0xffffffffu, mx, 1));
            mx = fmaxf(mx, __shfl_xor_sync(0xffffffffu, mx, 2));
            mx = fmaxf(mx, __shfl_xor_sync(0xffffffffu, mx, 4));
            mx = fmaxf(mx, __shfl_xor_sync(0xffffffffu, mx, 8));
            float mnew = fmaxf(m_r[r], mx);
            float corr = __expf(m_r[r] - mnew);
            m_r[r] = mnew;
            float rs = 0.0f;
#pragma unroll
            for (int c = 0; c < 4; c++) {
                float e = __expf(s[r][c] - mnew);
                s[r][c] = e;
                rs += e;
            }
            rs += __shfl_xor_sync(0xffffffffu, rs, 1);
            rs += __shfl_xor_sync(0xffffffffu, rs, 2);
            rs += __shfl_xor_sync(0xffffffffu, rs, 4);
            rs += __shfl_xor_sync(0xffffffffu, rs, 8);
            l_r[r] = l_r[r] * corr + rs;
#pragma unroll
            for (int c = 0; c < 4; c++) acc[r][c] *= corr;
        }

        __syncthreads();  // all S-GEMM reads of KPt done before overwriting with P^T

        // Dropout mask (exact JAX partitionable threefry, bits1^bits2) + store P^T into KPt
#pragma unroll
        for (int r = 0; r < 4; r++) {
            uint32_t ibits = hbase | ((uint32_t)(iBase + 4 * ty + r) << 12);
#pragma unroll
            for (int c = 0; c < 4; c++) {
                int jloc = 4 * tx + c;
                uint32_t e = ibits | (uint32_t)(j0 + jloc);
                float pe = keep_mask(e) ? s[r][c] : 0.0f;
                // P^T row = jloc, col = i (4*ty+r): chunk = ty ^ (jloc&15), word = r
                KPt[(jloc << 6) + ((ty ^ (jloc & 15)) << 2) + r] = pe;
            }
        }
        __syncthreads();

        // acc += P^T' V  (contraction over j)
#pragma unroll 16
        for (int j = 0; j < 64; j++) {
            float4 pv4 = *reinterpret_cast<const float4*>(&KPt[(j << 6) + ((ty ^ (j & 15)) << 2)]);
            float4 vv4 = *reinterpret_cast<const float4*>(&Vs[(j << 6) + (tx << 2)]);
            float pv[4] = {pv4.x, pv4.y, pv4.z, pv4.w};
            float vv[4] = {vv4.x, vv4.y, vv4.z, vv4.w};
#pragma unroll
            for (int r = 0; r < 4; r++)
#pragma unroll
                for (int c = 0; c < 4; c++) acc[r][c] = fmaf(pv[r], vv[c], acc[r][c]);
        }
    }

    // Finalize: out = acc / (l * 0.9), scattered per the reference reshape chain:
    // attn_out[h, n, d] -> out_flat[ ((n&255)*16 + h)*1024 + (n>>8)*64 + d ]
#pragma unroll
    for (int r = 0; r < 4; r++) {
        int n = iBase + 4 * ty + r;
        float inv = 1.0f / (l_r[r] * 0.9f);
        int obase = ((n & 255) * 16 + h) * 1024 + (n >> 8) * 64 + 4 * tx;
        float4 o;
        o.x = acc[r][0] * inv;
        o.y = acc[r][1] * inv;
        o.z = acc[r][2] * inv;
        o.w = acc[r][3] * inv;
        *reinterpret_cast<float4*>(out + obase) = o;
    }
}

extern "C" void kernel_launch(void* const* d_in, const int* in_sizes, int n_in,
                              void* d_out, int out_size)
{
    const float* q = (const float*)d_in[0];
    const float* k = (const float*)d_in[1];
    const float* v = (const float*)d_in[2];
    float* out = (float*)d_out;
    dim3 grid(NSEQ / BM, NHEAD);
    attn_kernel<<<grid, 256>>>(q, k, v, out);
}

// round 6
// speedup vs baseline: 2.0021x; 2.0021x over previous
#include <cuda_runtime.h>
#include <cuda_fp16.h>
#include <cstdint>

// mma.sync (HMMA fallback) flash attention, split-fp16 (hi+lo) both GEMMs,
// exact JAX threefry dropout (partitionable, bits1^bits2).
// B=1, S=4096, H=16, D=64. BM=128 (8 warps x 16 rows), BN=64 keys/tile.

#define NSEQ 4096
#define NHEAD 16

// ---------------- threefry2x32, key (0,42), draw = bits1 ^ bits2 ----------------
__device__ __forceinline__ void tf_g0(uint32_t& a, uint32_t& b) {
    a += b; b = __funnelshift_l(b, b, 13); b ^= a;
    a += b; b = __funnelshift_l(b, b, 15); b ^= a;
    a += b; b = __funnelshift_l(b, b, 26); b ^= a;
    a += b; b = __funnelshift_l(b, b, 6);  b ^= a;
}
__device__ __forceinline__ void tf_g1(uint32_t& a, uint32_t& b) {
    a += b; b = __funnelshift_l(b, b, 17); b ^= a;
    a += b; b = __funnelshift_l(b, b, 29); b ^= a;
    a += b; b = __funnelshift_l(b, b, 16); b ^= a;
    a += b; b = __funnelshift_l(b, b, 24); b ^= a;
}
__device__ __forceinline__ bool keep_mask(uint32_t e) {
    uint32_t a = 0u;
    uint32_t b = e + 42u;
    tf_g0(a, b); a += 42u;          b += 0x1BD11BF1u;
    tf_g1(a, b); a += 0x1BD11BF0u;  b += 2u;
    tf_g0(a, b);                    b += 45u;
    tf_g1(a, b); a += 42u;          b += 0x1BD11BF4u;
    tf_g0(a, b); a += 0x1BD11BF0u;  b += 5u;
    return ((a ^ b) >> 9) < 7549747u;
}

// ---------------- smem swizzle: 64-half rows (128B), XOR 16B-chunk swizzle ----------------
__device__ __forceinline__ int swz(int row, int col) {
    return (row << 6) + ((((col >> 3) ^ (row & 7)) << 3) | (col & 7));
}
__device__ __forceinline__ uint32_t sptr(const void* p) {
    return (uint32_t)__cvta_generic_to_shared(p);
}
__device__ __forceinline__ void ldsm4(uint32_t& r0, uint32_t& r1, uint32_t& r2, uint32_t& r3, uint32_t a) {
    asm volatile("ldmatrix.sync.aligned.m8n8.x4.shared.b16 {%0,%1,%2,%3}, [%4];"
                 : "=r"(r0), "=r"(r1), "=r"(r2), "=r"(r3) : "r"(a));
}
__device__ __forceinline__ void ldsm4t(uint32_t& r0, uint32_t& r1, uint32_t& r2, uint32_t& r3, uint32_t a) {
    asm volatile("ldmatrix.sync.aligned.m8n8.x4.trans.shared.b16 {%0,%1,%2,%3}, [%4];"
                 : "=r"(r0), "=r"(r1), "=r"(r2), "=r"(r3) : "r"(a));
}
__device__ __forceinline__ void mma16816(float* c, const uint32_t* a, uint32_t b0, uint32_t b1) {
    asm volatile(
        "mma.sync.aligned.m16n8k16.row.col.f32.f16.f16.f32 "
        "{%0,%1,%2,%3},{%4,%5,%6,%7},{%8,%9},{%0,%1,%2,%3};"
        : "+f"(c[0]), "+f"(c[1]), "+f"(c[2]), "+f"(c[3])
        : "r"(a[0]), "r"(a[1]), "r"(a[2]), "r"(a[3]), "r"(b0), "r"(b1));
}
// split x into fp16 hi + lo (packed pairs)
__device__ __forceinline__ void cvt_hilo(float x, float y, uint32_t& hi, uint32_t& lo) {
    __half2 h = __floats2half2_rn(x, y);
    float lx = x - __half2float(__low2half(h));
    float ly = y - __half2float(__high2half(h));
    __half2 l = __floats2half2_rn(lx, ly);
    hi = *reinterpret_cast<uint32_t*>(&h);
    lo = *reinterpret_cast<uint32_t*>(&l);
}

__global__ void __launch_bounds__(256, 1)
attn_mma(const float* __restrict__ q, const float* __restrict__ k,
         const float* __restrict__ v, float* __restrict__ out)
{
    // 32KB: [0]=Khi [1]=Klo [2]=Vhi [3]=Vlo (each 64x64 halves).
    // Q staged once: hi in [0..8192), lo in [8192..16384).
    __shared__ __align__(16) __half SH[4 * 64 * 64];
    __half* Khi = SH;
    __half* Klo = SH + 4096;
    __half* Vhi = SH + 8192;
    __half* Vlo = SH + 12288;

    const int tid = threadIdx.x;
    const int wid = tid >> 5;
    const int lane = tid & 31;
    const int qd = lane & 3;
    const int h = blockIdx.y;
    const int iBase = blockIdx.x * 128;

    // ---- stage Q (fp32 -> fp16 hi/lo) into SH, then grab A-fragments ----
#pragma unroll
    for (int it = 0; it < 8; it++) {
        int pos = tid + it * 256;          // 0..2047 float4s
        int row = pos >> 4;                // 0..127
        int c4 = pos & 15;
        float4 g = *reinterpret_cast<const float4*>(q + (size_t)(iBase + row) * 1024 + h * 64 + c4 * 4);
        uint32_t h0, l0, h1, l1;
        cvt_hilo(g.x, g.y, h0, l0);
        cvt_hilo(g.z, g.w, h1, l1);
        int idx = swz(row, c4 * 4);
        *reinterpret_cast<uint2*>(&SH[idx]) = make_uint2(h0, h1);
        *reinterpret_cast<uint2*>(&SH[8192 + idx]) = make_uint2(l0, l1);
    }
    __syncthreads();

    uint32_t qh[4][4], ql[4][4];
    {
        int r = 16 * wid + (lane & 15);
#pragma unroll
        for (int kk = 0; kk < 4; kk++) {
            int c = kk * 16 + ((lane >> 4) << 3);
            ldsm4(qh[kk][0], qh[kk][1], qh[kk][2], qh[kk][3], sptr(&SH[swz(r, c)]));
            ldsm4(ql[kk][0], ql[kk][1], ql[kk][2], ql[kk][3], sptr(&SH[8192 + swz(r, c)]));
        }
    }

    float o[8][4];
#pragma unroll
    for (int nt = 0; nt < 8; nt++)
#pragma unroll
        for (int c = 0; c < 4; c++) o[nt][c] = 0.0f;
    float lp0 = 0.0f, lp1 = 0.0f;

    const int n0 = iBase + 16 * wid + (lane >> 2);
    const uint32_t eb0 = ((uint32_t)h << 24) | ((uint32_t)n0 << 12);
    const uint32_t eb1 = eb0 + (8u << 12);
    const float C = 0.18033688011112042f;   // 0.125 * log2(e)

    for (int t = 0; t < 64; t++) {
        const int j0 = t * 64;

        // global loads for this tile (issued before the sync)
        float4 kg[4], vg[4];
        int krow[4], kc4[4];
#pragma unroll
        for (int it = 0; it < 4; it++) {
            int pos = tid + it * 256;
            krow[it] = pos >> 4;
            kc4[it] = pos & 15;
            size_t goff = (size_t)(j0 + krow[it]) * 1024 + h * 64 + kc4[it] * 4;
            kg[it] = *reinterpret_cast<const float4*>(k + goff);
            vg[it] = *reinterpret_cast<const float4*>(v + goff);
        }

        __syncthreads();   // previous tile's ldmatrix reads (and Q-frag loads) done

#pragma unroll
        for (int it = 0; it < 4; it++) {
            uint32_t h0, l0, h1, l1;
            int idx = swz(krow[it], kc4[it] * 4);
            cvt_hilo(kg[it].x, kg[it].y, h0, l0);
            cvt_hilo(kg[it].z, kg[it].w, h1, l1);
            *reinterpret_cast<uint2*>(&Khi[idx]) = make_uint2(h0, h1);
            *reinterpret_cast<uint2*>(&Klo[idx]) = make_uint2(l0, l1);
            cvt_hilo(vg[it].x, vg[it].y, h0, l0);
            cvt_hilo(vg[it].z, vg[it].w, h1, l1);
            *reinterpret_cast<uint2*>(&Vhi[idx]) = make_uint2(h0, h1);
            *reinterpret_cast<uint2*>(&Vlo[idx]) = make_uint2(l0, l1);
        }
        __syncthreads();

        // ---- MMA1: S = Q K^T (split fp16: qh*kh + qh*kl + ql*kh) ----
        float s[8][4];
#pragma unroll
        for (int nt = 0; nt < 8; nt++) {
#pragma unroll
            for (int c = 0; c < 4; c++) s[nt][c] = 0.0f;
            int brow = 8 * nt + (lane & 7);
#pragma unroll
            for (int kp = 0; kp < 2; kp++) {
                int bcol = 32 * kp + (lane & 24);
                uint32_t bh0, bh1, bh2, bh3, bl0, bl1, bl2, bl3;
                ldsm4(bh0, bh1, bh2, bh3, sptr(&Khi[swz(brow, bcol)]));
                ldsm4(bl0, bl1, bl2, bl3, sptr(&Klo[swz(brow, bcol)]));
                mma16816(s[nt], qh[2 * kp], bh0, bh1);
                mma16816(s[nt], qh[2 * kp], bl0, bl1);
                mma16816(s[nt], ql[2 * kp], bh0, bh1);
                mma16816(s[nt], qh[2 * kp + 1], bh2, bh3);
                mma16816(s[nt], qh[2 * kp + 1], bl2, bl3);
                mma16816(s[nt], ql[2 * kp + 1], bh2, bh3);
            }
        }

        // ---- epilogue: exp, threefry dropout, in-register repack to A-frags ----
        uint32_t ah[4][4], al[4][4];
#pragma unroll
        for (int nt = 0; nt < 8; nt++) {
            uint32_t jb = (uint32_t)(j0 + 8 * nt + 2 * qd);
            float p00 = exp2f(s[nt][0] * C);
            float p01 = exp2f(s[nt][1] * C);
            float p10 = exp2f(s[nt][2] * C);
            float p11 = exp2f(s[nt][3] * C);
            lp0 += p00 + p01;
            lp1 += p10 + p11;
            if (!keep_mask(eb0 + jb))      p00 = 0.0f;
            if (!keep_mask(eb0 + jb + 1u)) p01 = 0.0f;
            if (!keep_mask(eb1 + jb))      p10 = 0.0f;
            if (!keep_mask(eb1 + jb + 1u)) p11 = 0.0f;
            uint32_t h0, l0, h1, l1;
            cvt_hilo(p00, p01, h0, l0);
            cvt_hilo(p10, p11, h1, l1);
            int kk2 = nt >> 1, sel = (nt & 1) * 2;
            ah[kk2][sel + 0] = h0; ah[kk2][sel + 1] = h1;
            al[kk2][sel + 0] = l0; al[kk2][sel + 1] = l1;
        }

        // ---- MMA2: O += P V (split fp16: ph*vh + ph*vl + pl*vh) ----
#pragma unroll
        for (int nt = 0; nt < 8; nt++) {
            int bcol = 8 * nt;
#pragma unroll
            for (int kp = 0; kp < 2; kp++) {
                int brow = 32 * kp + lane;
                uint32_t vh0, vh1, vh2, vh3, vl0, vl1, vl2, vl3;
                ldsm4t(vh0, vh1, vh2, vh3, sptr(&Vhi[swz(brow, bcol)]));
                ldsm4t(vl0, vl1, vl2, vl3, sptr(&Vlo[swz(brow, bcol)]));
                mma16816(o[nt], ah[2 * kp], vh0, vh1);
                mma16816(o[nt], ah[2 * kp], vl0, vl1);
                mma16816(o[nt], al[2 * kp], vh0, vh1);
                mma16816(o[nt], ah[2 * kp + 1], vh2, vh3);
                mma16816(o[nt], ah[2 * kp + 1], vl2, vl3);
                mma16816(o[nt], al[2 * kp + 1], vh2, vh3);
            }
        }
    }

    // row-sum reduction within each quad (same row, 4 threads over columns)
    lp0 += __shfl_xor_sync(0xffffffffu, lp0, 1);
    lp0 += __shfl_xor_sync(0xffffffffu, lp0, 2);
    lp1 += __shfl_xor_sync(0xffffffffu, lp1, 1);
    lp1 += __shfl_xor_sync(0xffffffffu, lp1, 2);
    const float inv0 = 1.0f / (lp0 * 0.9f);
    const float inv1 = 1.0f / (lp1 * 0.9f);

    // scatter per reference reshape chain: out[((n&255)*16+h)*1024 + (n>>8)*64 + dv]
    const int n1 = n0 + 8;
    float* ob0 = out + (size_t)((n0 & 255) * 16 + h) * 1024 + (n0 >> 8) * 64;
    float* ob1 = out + (size_t)((n1 & 255) * 16 + h) * 1024 + (n1 >> 8) * 64;
#pragma unroll
    for (int nt = 0; nt < 8; nt++) {
        int dv = 8 * nt + 2 * qd;
        *reinterpret_cast<float2*>(ob0 + dv) = make_float2(o[nt][0] * inv0, o[nt][1] * inv0);
        *reinterpret_cast<float2*>(ob1 + dv) = make_float2(o[nt][2] * inv1, o[nt][3] * inv1);
    }
}

extern "C" void kernel_launch(void* const* d_in, const int* in_sizes, int n_in,
                              void* d_out, int out_size)
{
    const float* q = (const float*)d_in[0];
    const float* k = (const float*)d_in[1];
    const float* v = (const float*)d_in[2];
    float* out = (float*)d_out;
    dim3 grid(NSEQ / 128, NHEAD);
    attn_mma<<<grid, 256>>>(q, k, v, out);
}